// round 3
// baseline (speedup 1.0000x reference)
#include <cuda_runtime.h>
#include <math.h>
#include <stdint.h>

#define NN 1000
#define FF 64
#define BTOT 192          // B*T
#define EE 16000
#define EPAD 20000        // per-node padded-to-4 edge lists (16000 + <=3*1000)
#define NTERMS 9
#define KC (NTERMS*FF)    // 576
#define MROWS (BTOT*NN)   // 192000
#define LDIM 768000       // T*N*F
#define CC 10
#define BB 16
#define LN_EPS 1e-5f
#define SLAB_ROWS 1008    // 1000 real + zero sentinel rows
#define SLAB_BYTES (SLAB_ROWS * 32 * 4)

// ---------------- static device scratch ----------------
__device__ float g_basis[(size_t)MROWS * KC];   // 442 MB: 9 Chebyshev terms, interleaved
__device__ float g_hn[(size_t)MROWS * FF];      // 49 MB: post-LN hidden
__device__ float g_Wcat[KC * 128];              // stacked weights (z|h), tf32-rounded
__device__ int   g_cnt_src[NN], g_cnt_dst[NN];
__device__ int   g_fill_src[NN], g_fill_dst[NN];
__device__ int   g_pptr_src[NN + 1], g_pptr_dst[NN + 1];  // padded CSR offsets (mult of 4)
__device__ __align__(16) unsigned short g_i16_dst[EPAD];  // by-dst, stores src (sentinel=1000)
__device__ __align__(16) unsigned short g_i16_src[EPAD];  // by-src, stores dst (sentinel=1000)
__device__ float g_inv_in[NN], g_inv_out[NN];

__device__ __forceinline__ uint32_t f2tf32(float f) {
    uint32_t u;
    asm("cvt.rna.tf32.f32 %0, %1;" : "=r"(u) : "f"(f));
    return u;
}

__device__ __forceinline__ void mma_tf32(float c[4], const uint32_t a[4],
                                         uint32_t b0, uint32_t b1) {
    asm volatile(
        "mma.sync.aligned.m16n8k8.row.col.f32.tf32.tf32.f32 "
        "{%0,%1,%2,%3}, {%4,%5,%6,%7}, {%8,%9}, {%0,%1,%2,%3};"
        : "+f"(c[0]), "+f"(c[1]), "+f"(c[2]), "+f"(c[3])
        : "r"(a[0]), "r"(a[1]), "r"(a[2]), "r"(a[3]), "r"(b0), "r"(b1));
}

// ---------------- CSR construction ----------------
__global__ void init_counts_kernel() {
    int i = blockIdx.x * blockDim.x + threadIdx.x;
    if (i < NN) {
        g_cnt_src[i] = 0; g_cnt_dst[i] = 0;
        g_fill_src[i] = 0; g_fill_dst[i] = 0;
    }
    if (i < EPAD) { g_i16_dst[i] = (unsigned short)NN; g_i16_src[i] = (unsigned short)NN; }
}

__global__ void degree_kernel(const int* __restrict__ ei) {
    int e = blockIdx.x * blockDim.x + threadIdx.x;
    if (e < EE) {
        atomicAdd(&g_cnt_src[ei[e]], 1);
        atomicAdd(&g_cnt_dst[ei[EE + e]], 1);
    }
}

__global__ void scan_kernel() {
    if (threadIdx.x == 0) {
        int s = 0;
        for (int n = 0; n < NN; n++) { g_pptr_src[n] = s; s += (g_cnt_src[n] + 3) & ~3; }
        g_pptr_src[NN] = s;
        s = 0;
        for (int n = 0; n < NN; n++) { g_pptr_dst[n] = s; s += (g_cnt_dst[n] + 3) & ~3; }
        g_pptr_dst[NN] = s;
    }
    for (int n = threadIdx.x; n < NN; n += blockDim.x) {
        g_inv_out[n] = 1.0f / (float)g_cnt_src[n];
        g_inv_in[n]  = 1.0f / (float)g_cnt_dst[n];
    }
}

__global__ void fill_kernel(const int* __restrict__ ei) {
    int e = blockIdx.x * blockDim.x + threadIdx.x;
    if (e < EE) {
        int s = ei[e], d = ei[EE + e];
        int p = atomicAdd(&g_fill_dst[d], 1);
        g_i16_dst[g_pptr_dst[d] + p] = (unsigned short)s;
        int q = atomicAdd(&g_fill_src[s], 1);
        g_i16_src[g_pptr_src[s] + q] = (unsigned short)d;
    }
}

// ---------------- weight stacking ----------------
__global__ void wcat_kernel(const float* __restrict__ Wz, const float* __restrict__ Wh) {
    int t = blockIdx.x * blockDim.x + threadIdx.x;
    if (t >= KC * 128) return;
    int kk = t >> 7;            // [0,576)
    int j  = t & 127;
    int term = kk / FF;
    int ci   = kk % FF;
    const float* W = (j < FF) ? Wz : Wh;
    int co = (j < FF) ? j : j - FF;
    float v;
    if (term == 0) {
        v = W[((0 * 5 + 0) * 128 + ci) * 64 + co] + W[((1 * 5 + 0) * 128 + ci) * 64 + co];
    } else if (term <= 4) {
        v = W[((0 * 5 + term) * 128 + ci) * 64 + co];
    } else {
        v = W[((1 * 5 + (term - 4)) * 128 + ci) * 64 + co];
    }
    g_Wcat[kk * 128 + j] = __uint_as_float(f2tf32(v));
}

// ---------------- basis term 0 = X ----------------
__global__ void copy_t0_kernel(const float* __restrict__ x) {
    int i = blockIdx.x * blockDim.x + threadIdx.x;   // float4 index
    if (i < MROWS * FF / 4) {
        int r = i >> 4, f4 = i & 15;
        const float4 v = reinterpret_cast<const float4*>(x)[i];
        *reinterpret_cast<float4*>(&g_basis[(size_t)r * KC + f4 * 4]) = v;
    }
}

// ---------------- smem-staged sparse propagation ----------------
// grid (BTOT, 2): blockIdx.x = bt slice, blockIdx.y = 32-feature half.
// Input term slab staged in shared (pre-scaled for out-chain). Inner loop:
// 1 uint2 read = 4 uint16 edge indices, 4 conflict-free 128B LDS wavefronts.
__global__ void __launch_bounds__(512) prop_out_s(int term_in, int term_out,
                                                  int term_sub, float alpha) {
    extern __shared__ float slab[];   // [SLAB_ROWS][32]
    int bt = blockIdx.x, f0 = blockIdx.y * 32;
    int tid = threadIdx.x, lane = tid & 31, w = tid >> 5;
    const int NW = 512 >> 5;
    const float* src = g_basis + (size_t)bt * NN * KC + term_in * FF + f0;
    for (int n = w; n < NN; n += NW)
        slab[n * 32 + lane] = __ldg(src + (size_t)n * KC + lane) * g_inv_out[n];
    for (int n = NN + w; n < SLAB_ROWS; n += NW)
        slab[n * 32 + lane] = 0.f;
    __syncthreads();

    float* obase = g_basis + (size_t)bt * NN * KC;
    for (int n = w; n < NN; n += NW) {
        int b0 = g_pptr_dst[n], b1 = g_pptr_dst[n + 1];
        float acc = 0.f;
        for (int e = b0; e < b1; e += 4) {
            uint2 q = __ldg(reinterpret_cast<const uint2*>(g_i16_dst + e));
            int i0 = q.x & 0xffff, i1 = q.x >> 16;
            int i2 = q.y & 0xffff, i3 = q.y >> 16;
            acc += slab[i0 * 32 + lane] + slab[i1 * 32 + lane]
                 + slab[i2 * 32 + lane] + slab[i3 * 32 + lane];
        }
        float res = alpha * acc;
        size_t ro = (size_t)n * KC + f0 + lane;
        if (term_sub >= 0) res -= obase[ro + term_sub * FF];
        obase[ro + term_out * FF] = res;
    }
}

__global__ void __launch_bounds__(512) prop_in_s(int term_in, int term_out,
                                                 int term_sub, float alpha) {
    extern __shared__ float slab[];
    int bt = blockIdx.x, f0 = blockIdx.y * 32;
    int tid = threadIdx.x, lane = tid & 31, w = tid >> 5;
    const int NW = 512 >> 5;
    const float* src = g_basis + (size_t)bt * NN * KC + term_in * FF + f0;
    for (int n = w; n < NN; n += NW)
        slab[n * 32 + lane] = __ldg(src + (size_t)n * KC + lane);
    for (int n = NN + w; n < SLAB_ROWS; n += NW)
        slab[n * 32 + lane] = 0.f;
    __syncthreads();

    float* obase = g_basis + (size_t)bt * NN * KC;
    for (int n = w; n < NN; n += NW) {
        int b0 = g_pptr_src[n], b1 = g_pptr_src[n + 1];
        float acc = 0.f;
        for (int e = b0; e < b1; e += 4) {
            uint2 q = __ldg(reinterpret_cast<const uint2*>(g_i16_src + e));
            int i0 = q.x & 0xffff, i1 = q.x >> 16;
            int i2 = q.y & 0xffff, i3 = q.y >> 16;
            acc += slab[i0 * 32 + lane] + slab[i1 * 32 + lane]
                 + slab[i2 * 32 + lane] + slab[i3 * 32 + lane];
        }
        float res = alpha * g_inv_in[n] * acc;
        size_t ro = (size_t)n * KC + f0 + lane;
        if (term_sub >= 0) res -= obase[ro + term_sub * FF];
        obase[ro + term_out * FF] = res;
    }
}

// ---------------- tf32 tensor-core GEMM (192000x576 @ 576x128) + gate + LN ----------------
#define TM 128
#define TKC 16
__global__ void __launch_bounds__(256) gemm_tc_kernel(
    const float* __restrict__ bz, const float* __restrict__ bh,
    const float* __restrict__ lng, const float* __restrict__ lnb)
{
    __shared__ uint32_t As[TM][TKC + 1];
    __shared__ uint32_t Bs[TKC][132];

    int tid = threadIdx.x;
    int w = tid >> 5, lane = tid & 31;
    int g = lane >> 2, tg = lane & 3;
    int block_row = blockIdx.x * TM;

    float acc[16][4];
#pragma unroll
    for (int j = 0; j < 16; j++)
#pragma unroll
        for (int i = 0; i < 4; i++) acc[j][i] = 0.f;

    int arow = tid >> 1;            // A-load: 2 threads per row, 8 floats each
    int acol = (tid & 1) * 8;
    int brow = tid >> 4;            // B-load: 16 threads per row, 8 floats each
    int bcol = (tid & 15) * 8;
    const float* aptr = &g_basis[(size_t)(block_row + arow) * KC + acol];
    const float* bptr = &g_Wcat[brow * 128 + bcol];

    // prologue prefetch
    float4 pa0 = *reinterpret_cast<const float4*>(aptr);
    float4 pa1 = *reinterpret_cast<const float4*>(aptr + 4);
    float4 pb0 = *reinterpret_cast<const float4*>(bptr);
    float4 pb1 = *reinterpret_cast<const float4*>(bptr + 4);

    for (int k0 = 0; k0 < KC; k0 += TKC) {
        As[arow][acol + 0] = f2tf32(pa0.x); As[arow][acol + 1] = f2tf32(pa0.y);
        As[arow][acol + 2] = f2tf32(pa0.z); As[arow][acol + 3] = f2tf32(pa0.w);
        As[arow][acol + 4] = f2tf32(pa1.x); As[arow][acol + 5] = f2tf32(pa1.y);
        As[arow][acol + 6] = f2tf32(pa1.z); As[arow][acol + 7] = f2tf32(pa1.w);
        Bs[brow][bcol + 0] = __float_as_uint(pb0.x); Bs[brow][bcol + 1] = __float_as_uint(pb0.y);
        Bs[brow][bcol + 2] = __float_as_uint(pb0.z); Bs[brow][bcol + 3] = __float_as_uint(pb0.w);
        Bs[brow][bcol + 4] = __float_as_uint(pb1.x); Bs[brow][bcol + 5] = __float_as_uint(pb1.y);
        Bs[brow][bcol + 6] = __float_as_uint(pb1.z); Bs[brow][bcol + 7] = __float_as_uint(pb1.w);
        __syncthreads();

        if (k0 + TKC < KC) {   // prefetch next tile while MMAs run
            pa0 = *reinterpret_cast<const float4*>(aptr + k0 + TKC);
            pa1 = *reinterpret_cast<const float4*>(aptr + k0 + TKC + 4);
            pb0 = *reinterpret_cast<const float4*>(bptr + (k0 + TKC) * 128);
            pb1 = *reinterpret_cast<const float4*>(bptr + (k0 + TKC) * 128 + 4);
        }

#pragma unroll
        for (int kb = 0; kb < TKC; kb += 8) {
            uint32_t a[4];
            a[0] = As[w * 16 + g][kb + tg];
            a[1] = As[w * 16 + g + 8][kb + tg];
            a[2] = As[w * 16 + g][kb + tg + 4];
            a[3] = As[w * 16 + g + 8][kb + tg + 4];
#pragma unroll
            for (int j = 0; j < 16; j++) {
                uint32_t bb0 = Bs[kb + tg][j * 8 + g];
                uint32_t bb1 = Bs[kb + tg + 4][j * 8 + g];
                mma_tf32(acc[j], a, bb0, bb1);
            }
        }
        __syncthreads();
    }

    // ---- epilogue: gate + LayerNorm, register-resident ----
#pragma unroll
    for (int rs = 0; rs < 2; rs++) {
        int row = block_row + w * 16 + g + rs * 8;
        float gv[8][2];
        float sum = 0.f, sq = 0.f;
#pragma unroll
        for (int j = 0; j < 8; j++) {
#pragma unroll
            for (int s = 0; s < 2; s++) {
                int col = j * 8 + tg * 2 + s;
                float vz = acc[j][rs * 2 + s] + __ldg(bz + col);
                float vh = acc[j + 8][rs * 2 + s] + __ldg(bh + col);
                float z = 1.f / (1.f + expf(-vz));
                float val = fmaxf(0.f, (1.f - z) * tanhf(vh));
                gv[j][s] = val;
                sum += val; sq += val * val;
            }
        }
        sum += __shfl_xor_sync(0xffffffffu, sum, 1);
        sq  += __shfl_xor_sync(0xffffffffu, sq, 1);
        sum += __shfl_xor_sync(0xffffffffu, sum, 2);
        sq  += __shfl_xor_sync(0xffffffffu, sq, 2);
        float mu = sum * (1.f / 64.f);
        float var = fmaxf(sq * (1.f / 64.f) - mu * mu, 0.f);
        float rstd = rsqrtf(var + LN_EPS);
        float* orow = g_hn + (size_t)row * FF;
#pragma unroll
        for (int j = 0; j < 8; j++) {
            int col = j * 8 + tg * 2;
            float2 o;
            o.x = (gv[j][0] - mu) * rstd * __ldg(lng + col)     + __ldg(lnb + col);
            o.y = (gv[j][1] - mu) * rstd * __ldg(lng + col + 1) + __ldg(lnb + col + 1);
            *reinterpret_cast<float2*>(orow + col) = o;
        }
    }
}

// ---------------- final linear head ----------------
__global__ void out_init_kernel(float* __restrict__ out, const float* __restrict__ lb) {
    int i = threadIdx.x;
    if (i < BB * CC) out[i] = lb[i % CC];
}

#define CH 1024
__global__ void __launch_bounds__(256) final_linear_kernel(
    const float* __restrict__ lin_w, float* __restrict__ out)
{
    __shared__ float ws[CC][CH];
    __shared__ float red[8][CC];
    int base = blockIdx.x * CH;   // 750 blocks * 1024 = 768000
    int tid = threadIdx.x;
    for (int i = tid; i < CC * CH; i += 256) {
        int c = i / CH, o = i % CH;
        ws[c][o] = lin_w[(size_t)c * LDIM + base + o];
    }
    __syncthreads();
    int w = tid >> 5, lane = tid & 31;
    for (int b = 0; b < BB; b++) {
        float a[CC];
#pragma unroll
        for (int c = 0; c < CC; c++) a[c] = 0.f;
        const float* hb = g_hn + (size_t)b * LDIM + base;
        for (int i = tid; i < CH; i += 256) {
            float hv = hb[i];
#pragma unroll
            for (int c = 0; c < CC; c++) a[c] += hv * ws[c][i];
        }
#pragma unroll
        for (int o = 16; o; o >>= 1)
#pragma unroll
            for (int c = 0; c < CC; c++) a[c] += __shfl_down_sync(0xffffffffu, a[c], o);
        if (lane == 0)
#pragma unroll
            for (int c = 0; c < CC; c++) red[w][c] = a[c];
        __syncthreads();
        if (tid < CC) {
            float s = 0.f;
#pragma unroll
            for (int ww = 0; ww < 8; ww++) s += red[ww][tid];
            atomicAdd(&out[b * CC + tid], s);
        }
        __syncthreads();
    }
}

// ---------------- launch ----------------
extern "C" void kernel_launch(void* const* d_in, const int* in_sizes, int n_in,
                              void* d_out, int out_size) {
    const float* x    = (const float*)d_in[0];
    const int*   ei   = (const int*)d_in[1];
    const float* Wz   = (const float*)d_in[2];
    const float* bz   = (const float*)d_in[3];
    // d_in[4], d_in[5] = W_r, b_r -> dead code (h0 == 0)
    const float* Wh   = (const float*)d_in[6];
    const float* bh   = (const float*)d_in[7];
    const float* lng  = (const float*)d_in[8];
    const float* lnb  = (const float*)d_in[9];
    const float* linw = (const float*)d_in[10];
    const float* linb = (const float*)d_in[11];
    float* out = (float*)d_out;

    static bool attr_done = false;
    if (!attr_done) {
        cudaFuncSetAttribute(prop_out_s, cudaFuncAttributeMaxDynamicSharedMemorySize, SLAB_BYTES);
        cudaFuncSetAttribute(prop_in_s,  cudaFuncAttributeMaxDynamicSharedMemorySize, SLAB_BYTES);
        attr_done = true;
    }

    init_counts_kernel<<<(EPAD + 255) / 256, 256>>>();
    degree_kernel<<<(EE + 255) / 256, 256>>>(ei);
    scan_kernel<<<1, 256>>>();
    fill_kernel<<<(EE + 255) / 256, 256>>>(ei);
    wcat_kernel<<<(KC * 128 + 255) / 256, 256>>>(Wz, Wh);
    copy_t0_kernel<<<(MROWS * FF / 4 + 255) / 256, 256>>>(x);

    dim3 pgrid(BTOT, 2);
    // terms: 0=X, 1..4 = out-chain, 5..8 = in-chain (in-chain Tx0 history uses out-chain terms)
    prop_out_s<<<pgrid, 512, SLAB_BYTES>>>(0, 1, -1, 1.0f);
    prop_in_s <<<pgrid, 512, SLAB_BYTES>>>(0, 5, -1, 1.0f);
    prop_out_s<<<pgrid, 512, SLAB_BYTES>>>(1, 2, 0, 2.0f);
    prop_in_s <<<pgrid, 512, SLAB_BYTES>>>(5, 6, 0, 2.0f);
    prop_out_s<<<pgrid, 512, SLAB_BYTES>>>(2, 3, 1, 2.0f);
    prop_in_s <<<pgrid, 512, SLAB_BYTES>>>(6, 7, 1, 2.0f);
    prop_out_s<<<pgrid, 512, SLAB_BYTES>>>(3, 4, 2, 2.0f);
    prop_in_s <<<pgrid, 512, SLAB_BYTES>>>(7, 8, 2, 2.0f);

    gemm_tc_kernel<<<MROWS / TM, 256>>>(bz, bh, lng, lnb);

    out_init_kernel<<<1, 256>>>(out, linb);
    final_linear_kernel<<<LDIM / CH, 256>>>(linw, out);
}

// round 4
// speedup vs baseline: 1.9625x; 1.9625x over previous
#include <cuda_runtime.h>
#include <math.h>
#include <stdint.h>

#define NN 1000
#define FF 64
#define BTOT 192          // B*T
#define EE 16000
#define EPAD 20000        // per-node padded-to-4 edge lists
#define NTERMS 9
#define KC (NTERMS*FF)    // 576
#define MROWS (BTOT*NN)   // 192000
#define LDIM 768000       // T*N*F
#define CC 10
#define BB 16
#define LN_EPS 1e-5f

// ---------------- static device scratch ----------------
__device__ float g_basis[(size_t)MROWS * KC];   // 442 MB: 9 Chebyshev terms, interleaved
__device__ float g_hn[(size_t)MROWS * FF];      // 49 MB: post-LN hidden
__device__ float g_Wcat[KC * 128];              // stacked weights (z|h), tf32-rounded
__device__ int   g_pptr_src[NN + 1], g_pptr_dst[NN + 1];  // padded CSR offsets (mult of 4)
__device__ __align__(16) unsigned short g_i16_dst[EPAD];  // by-dst, stores src (pad: idx 0, w 0)
__device__ __align__(16) unsigned short g_i16_src[EPAD];  // by-src, stores dst
__device__ __align__(16) float g_wq_dst[EPAD];            // 1/deg_out[src], pads 0
__device__ __align__(16) float g_wq_src[EPAD];            // 1.0, pads 0
__device__ float g_inv_in[NN];

__device__ __forceinline__ uint32_t f2tf32(float f) {
    uint32_t u;
    asm("cvt.rna.tf32.f32 %0, %1;" : "=r"(u) : "f"(f));
    return u;
}

__device__ __forceinline__ void mma_tf32(float c[4], const uint32_t a[4],
                                         uint32_t b0, uint32_t b1) {
    asm volatile(
        "mma.sync.aligned.m16n8k8.row.col.f32.tf32.tf32.f32 "
        "{%0,%1,%2,%3}, {%4,%5,%6,%7}, {%8,%9}, {%0,%1,%2,%3};"
        : "+f"(c[0]), "+f"(c[1]), "+f"(c[2]), "+f"(c[3])
        : "r"(a[0]), "r"(a[1]), "r"(a[2]), "r"(a[3]), "r"(b0), "r"(b1));
}

// ---------------- single-block CSR setup ----------------
__global__ void __launch_bounds__(1024) setup_kernel(const int* __restrict__ ei) {
    __shared__ int s_cnt_src[NN], s_cnt_dst[NN];
    __shared__ int s_ptr_src[NN + 1], s_ptr_dst[NN + 1];
    __shared__ int s_fill_src[NN], s_fill_dst[NN];
    int tid = threadIdx.x;
    for (int i = tid; i < NN; i += 1024) {
        s_cnt_src[i] = 0; s_cnt_dst[i] = 0;
        s_fill_src[i] = 0; s_fill_dst[i] = 0;
    }
    __syncthreads();
    for (int e = tid; e < EE; e += 1024) {
        atomicAdd(&s_cnt_src[ei[e]], 1);
        atomicAdd(&s_cnt_dst[ei[EE + e]], 1);
    }
    __syncthreads();
    if (tid == 0) {
        int s = 0, t = 0;
        for (int n = 0; n < NN; n++) {
            s_ptr_src[n] = s; s += (s_cnt_src[n] + 3) & ~3;
            s_ptr_dst[n] = t; t += (s_cnt_dst[n] + 3) & ~3;
        }
        s_ptr_src[NN] = s; s_ptr_dst[NN] = t;
    }
    __syncthreads();
    for (int i = tid; i <= NN; i += 1024) {
        g_pptr_src[i] = s_ptr_src[i];
        g_pptr_dst[i] = s_ptr_dst[i];
    }
    for (int n = tid; n < NN; n += 1024)
        g_inv_in[n] = 1.0f / (float)s_cnt_dst[n];
    for (int i = tid; i < EPAD; i += 1024) {
        g_i16_dst[i] = 0; g_i16_src[i] = 0;
        g_wq_dst[i] = 0.f; g_wq_src[i] = 0.f;
    }
    __syncthreads();
    for (int e = tid; e < EE; e += 1024) {
        int s = ei[e], d = ei[EE + e];
        int p = atomicAdd(&s_fill_dst[d], 1);
        int slot = s_ptr_dst[d] + p;
        g_i16_dst[slot] = (unsigned short)s;
        g_wq_dst[slot] = 1.0f / (float)s_cnt_src[s];   // 1/deg_out[src]
        int q = atomicAdd(&s_fill_src[s], 1);
        int slot2 = s_ptr_src[s] + q;
        g_i16_src[slot2] = (unsigned short)d;
        g_wq_src[slot2] = 1.0f;
    }
}

// ---------------- weight stacking ----------------
__global__ void wcat_kernel(const float* __restrict__ Wz, const float* __restrict__ Wh) {
    int t = blockIdx.x * blockDim.x + threadIdx.x;
    if (t >= KC * 128) return;
    int kk = t >> 7;            // [0,576)
    int j  = t & 127;
    int term = kk / FF;
    int ci   = kk % FF;
    const float* W = (j < FF) ? Wz : Wh;
    int co = (j < FF) ? j : j - FF;
    float v;
    if (term == 0) {
        v = W[((0 * 5 + 0) * 128 + ci) * 64 + co] + W[((1 * 5 + 0) * 128 + ci) * 64 + co];
    } else if (term <= 4) {
        v = W[((0 * 5 + term) * 128 + ci) * 64 + co];
    } else {
        v = W[((1 * 5 + (term - 4)) * 128 + ci) * 64 + co];
    }
    g_Wcat[kk * 128 + j] = __uint_as_float(f2tf32(v));
}

// ---------------- basis term 0 = X ----------------
__global__ void copy_t0_kernel(const float* __restrict__ x) {
    int i = blockIdx.x * blockDim.x + threadIdx.x;   // float4 index
    if (i < MROWS * FF / 4) {
        int r = i >> 4, f4 = i & 15;
        const float4 v = reinterpret_cast<const float4*>(x)[i];
        *reinterpret_cast<float4*>(&g_basis[(size_t)r * KC + f4 * 4]) = v;
    }
}

// ---------------- vectorized gather propagation (both directions in one launch) ----------------
// grid (MROWS/8, 2): y=0 -> out-chain (dst-grouped edges, pre-scaled weights),
//                    y=1 -> in-chain (src-grouped edges, w=1, post-scale 1/deg_in[n]).
// block 128 thr = 8 groups of 16 lanes; group handles one (bt,node); lane covers 4 features.
// Edge lists padded to multiples of 4 with w=0 entries -> branch-free quad iterations.
__global__ void __launch_bounds__(128) prop_pair_kernel(
    int tin_o, int tin_i, int tout_o, int tout_i, int tsub, float alpha)
{
    int tid = threadIdx.x;
    int g = tid >> 4, l = tid & 15;
    int flat = blockIdx.x * 8 + g;        // [0, MROWS)
    int bt = flat / NN, n = flat - bt * NN;
    int dir = blockIdx.y;

    const unsigned short* idx;
    const float* wq;
    int b0, b1, tin, tout;
    if (dir == 0) {
        idx = g_i16_dst; wq = g_wq_dst;
        b0 = g_pptr_dst[n]; b1 = g_pptr_dst[n + 1];
        tin = tin_o; tout = tout_o;
    } else {
        idx = g_i16_src; wq = g_wq_src;
        b0 = g_pptr_src[n]; b1 = g_pptr_src[n + 1];
        tin = tin_i; tout = tout_i;
    }

    const char* base = (const char*)(g_basis + (size_t)bt * NN * KC + tin * FF) + l * 16;
    float4 acc = make_float4(0.f, 0.f, 0.f, 0.f);

    for (int e = b0; e < b1; e += 4) {
        uint2 q = *reinterpret_cast<const uint2*>(idx + e);
        float4 w = *reinterpret_cast<const float4*>(wq + e);
        int i0 = q.x & 0xffff, i1 = q.x >> 16;
        int i2 = q.y & 0xffff, i3 = q.y >> 16;
        float4 v0 = __ldg(reinterpret_cast<const float4*>(base + (size_t)i0 * (KC * 4)));
        float4 v1 = __ldg(reinterpret_cast<const float4*>(base + (size_t)i1 * (KC * 4)));
        float4 v2 = __ldg(reinterpret_cast<const float4*>(base + (size_t)i2 * (KC * 4)));
        float4 v3 = __ldg(reinterpret_cast<const float4*>(base + (size_t)i3 * (KC * 4)));
        acc.x += w.x * v0.x + w.y * v1.x + w.z * v2.x + w.w * v3.x;
        acc.y += w.x * v0.y + w.y * v1.y + w.z * v2.y + w.w * v3.y;
        acc.z += w.x * v0.z + w.y * v1.z + w.z * v2.z + w.w * v3.z;
        acc.w += w.x * v0.w + w.y * v1.w + w.z * v2.w + w.w * v3.w;
    }

    float scale = dir ? alpha * g_inv_in[n] : alpha;
    float4 r = make_float4(scale * acc.x, scale * acc.y, scale * acc.z, scale * acc.w);
    float* orow = g_basis + (size_t)flat * KC;
    if (tsub >= 0) {
        float4 s4 = *reinterpret_cast<const float4*>(orow + tsub * FF + l * 4);
        r.x -= s4.x; r.y -= s4.y; r.z -= s4.z; r.w -= s4.w;
    }
    *reinterpret_cast<float4*>(orow + tout * FF + l * 4) = r;
}

// ---------------- tf32 tensor-core GEMM (192000x576 @ 576x128) + gate + LN ----------------
#define TM 128
#define TKC 16
__global__ void __launch_bounds__(256) gemm_tc_kernel(
    const float* __restrict__ bz, const float* __restrict__ bh,
    const float* __restrict__ lng, const float* __restrict__ lnb)
{
    __shared__ uint32_t As[TM][TKC + 1];
    __shared__ uint32_t Bs[TKC][132];

    int tid = threadIdx.x;
    int w = tid >> 5, lane = tid & 31;
    int g = lane >> 2, tg = lane & 3;
    int block_row = blockIdx.x * TM;

    float acc[16][4];
#pragma unroll
    for (int j = 0; j < 16; j++)
#pragma unroll
        for (int i = 0; i < 4; i++) acc[j][i] = 0.f;

    int arow = tid >> 1;            // A-load: 2 threads per row, 8 floats each
    int acol = (tid & 1) * 8;
    int brow = tid >> 4;            // B-load: 16 threads per row, 8 floats each
    int bcol = (tid & 15) * 8;
    const float* aptr = &g_basis[(size_t)(block_row + arow) * KC + acol];
    const float* bptr = &g_Wcat[brow * 128 + bcol];

    for (int k0 = 0; k0 < KC; k0 += TKC) {
        float4 a0 = *reinterpret_cast<const float4*>(aptr + k0);
        float4 a1 = *reinterpret_cast<const float4*>(aptr + k0 + 4);
        As[arow][acol + 0] = f2tf32(a0.x); As[arow][acol + 1] = f2tf32(a0.y);
        As[arow][acol + 2] = f2tf32(a0.z); As[arow][acol + 3] = f2tf32(a0.w);
        As[arow][acol + 4] = f2tf32(a1.x); As[arow][acol + 5] = f2tf32(a1.y);
        As[arow][acol + 6] = f2tf32(a1.z); As[arow][acol + 7] = f2tf32(a1.w);
        float4 b0 = *reinterpret_cast<const float4*>(bptr + k0 * 128);
        float4 b1 = *reinterpret_cast<const float4*>(bptr + k0 * 128 + 4);
        Bs[brow][bcol + 0] = __float_as_uint(b0.x); Bs[brow][bcol + 1] = __float_as_uint(b0.y);
        Bs[brow][bcol + 2] = __float_as_uint(b0.z); Bs[brow][bcol + 3] = __float_as_uint(b0.w);
        Bs[brow][bcol + 4] = __float_as_uint(b1.x); Bs[brow][bcol + 5] = __float_as_uint(b1.y);
        Bs[brow][bcol + 6] = __float_as_uint(b1.z); Bs[brow][bcol + 7] = __float_as_uint(b1.w);
        __syncthreads();

#pragma unroll
        for (int kb = 0; kb < TKC; kb += 8) {
            uint32_t a[4];
            a[0] = As[w * 16 + g][kb + tg];
            a[1] = As[w * 16 + g + 8][kb + tg];
            a[2] = As[w * 16 + g][kb + tg + 4];
            a[3] = As[w * 16 + g + 8][kb + tg + 4];
#pragma unroll
            for (int j = 0; j < 16; j++) {
                uint32_t bb0 = Bs[kb + tg][j * 8 + g];
                uint32_t bb1 = Bs[kb + tg + 4][j * 8 + g];
                mma_tf32(acc[j], a, bb0, bb1);
            }
        }
        __syncthreads();
    }

    // ---- epilogue: gate + LayerNorm, register-resident ----
#pragma unroll
    for (int rs = 0; rs < 2; rs++) {
        int row = block_row + w * 16 + g + rs * 8;
        float gv[8][2];
        float sum = 0.f, sq = 0.f;
#pragma unroll
        for (int j = 0; j < 8; j++) {
#pragma unroll
            for (int s = 0; s < 2; s++) {
                int col = j * 8 + tg * 2 + s;
                float vz = acc[j][rs * 2 + s] + __ldg(bz + col);
                float vh = acc[j + 8][rs * 2 + s] + __ldg(bh + col);
                float z = 1.f / (1.f + expf(-vz));
                float val = fmaxf(0.f, (1.f - z) * tanhf(vh));
                gv[j][s] = val;
                sum += val; sq += val * val;
            }
        }
        sum += __shfl_xor_sync(0xffffffffu, sum, 1);
        sq  += __shfl_xor_sync(0xffffffffu, sq, 1);
        sum += __shfl_xor_sync(0xffffffffu, sum, 2);
        sq  += __shfl_xor_sync(0xffffffffu, sq, 2);
        float mu = sum * (1.f / 64.f);
        float var = fmaxf(sq * (1.f / 64.f) - mu * mu, 0.f);
        float rstd = rsqrtf(var + LN_EPS);
        float* orow = g_hn + (size_t)row * FF;
#pragma unroll
        for (int j = 0; j < 8; j++) {
            int col = j * 8 + tg * 2;
            float2 o;
            o.x = (gv[j][0] - mu) * rstd * __ldg(lng + col)     + __ldg(lnb + col);
            o.y = (gv[j][1] - mu) * rstd * __ldg(lng + col + 1) + __ldg(lnb + col + 1);
            *reinterpret_cast<float2*>(orow + col) = o;
        }
    }
}

// ---------------- final linear head ----------------
__global__ void out_init_kernel(float* __restrict__ out, const float* __restrict__ lb) {
    int i = threadIdx.x;
    if (i < BB * CC) out[i] = lb[i % CC];
}

#define CH 1024
__global__ void __launch_bounds__(256) final_linear_kernel(
    const float* __restrict__ lin_w, float* __restrict__ out)
{
    __shared__ float ws[CC][CH];
    __shared__ float red[8][CC];
    int base = blockIdx.x * CH;   // 750 blocks * 1024 = 768000
    int tid = threadIdx.x;
    for (int i = tid; i < CC * CH; i += 256) {
        int c = i / CH, o = i % CH;
        ws[c][o] = lin_w[(size_t)c * LDIM + base + o];
    }
    __syncthreads();
    int w = tid >> 5, lane = tid & 31;
    for (int b = 0; b < BB; b++) {
        float a[CC];
#pragma unroll
        for (int c = 0; c < CC; c++) a[c] = 0.f;
        const float* hb = g_hn + (size_t)b * LDIM + base;
        for (int i = tid; i < CH; i += 256) {
            float hv = hb[i];
#pragma unroll
            for (int c = 0; c < CC; c++) a[c] += hv * ws[c][i];
        }
#pragma unroll
        for (int o = 16; o; o >>= 1)
#pragma unroll
            for (int c = 0; c < CC; c++) a[c] += __shfl_down_sync(0xffffffffu, a[c], o);
        if (lane == 0)
#pragma unroll
            for (int c = 0; c < CC; c++) red[w][c] = a[c];
        __syncthreads();
        if (tid < CC) {
            float s = 0.f;
#pragma unroll
            for (int ww = 0; ww < 8; ww++) s += red[ww][tid];
            atomicAdd(&out[b * CC + tid], s);
        }
        __syncthreads();
    }
}

// ---------------- launch ----------------
extern "C" void kernel_launch(void* const* d_in, const int* in_sizes, int n_in,
                              void* d_out, int out_size) {
    const float* x    = (const float*)d_in[0];
    const int*   ei   = (const int*)d_in[1];
    const float* Wz   = (const float*)d_in[2];
    const float* bz   = (const float*)d_in[3];
    // d_in[4], d_in[5] = W_r, b_r -> dead code (h0 == 0)
    const float* Wh   = (const float*)d_in[6];
    const float* bh   = (const float*)d_in[7];
    const float* lng  = (const float*)d_in[8];
    const float* lnb  = (const float*)d_in[9];
    const float* linw = (const float*)d_in[10];
    const float* linb = (const float*)d_in[11];
    float* out = (float*)d_out;

    setup_kernel<<<1, 1024>>>(ei);                                   // launch 1
    wcat_kernel<<<(KC * 128 + 255) / 256, 256>>>(Wz, Wh);            // launch 2
    copy_t0_kernel<<<(MROWS * FF / 4 + 255) / 256, 256>>>(x);        // launch 3

    dim3 pgrid(MROWS / 8, 2);
    // terms: 0=X, 1..4 = out-chain, 5..8 = in-chain (shared Tx0 history = out-chain terms)
    prop_pair_kernel<<<pgrid, 128>>>(0, 0, 1, 5, -1, 1.0f);          // launch 4 (profiled slot)
    prop_pair_kernel<<<pgrid, 128>>>(1, 5, 2, 6, 0, 2.0f);
    prop_pair_kernel<<<pgrid, 128>>>(2, 6, 3, 7, 1, 2.0f);
    prop_pair_kernel<<<pgrid, 128>>>(3, 7, 4, 8, 2, 2.0f);

    gemm_tc_kernel<<<MROWS / TM, 256>>>(bz, bh, lng, lnb);

    out_init_kernel<<<1, 256>>>(out, linb);
    final_linear_kernel<<<LDIM / CH, 256>>>(linw, out);
}

// round 5
// speedup vs baseline: 2.2020x; 1.1220x over previous
#include <cuda_runtime.h>
#include <math.h>
#include <stdint.h>

#define NN 1000
#define FF 64
#define BTOT 192          // B*T
#define EE 16000
#define EPAD 20000        // per-node padded-to-4 edge lists
#define NTERMS 9
#define KC (NTERMS*FF)    // 576
#define MROWS (BTOT*NN)   // 192000
#define LDIM 768000       // T*N*F
#define CC 10
#define BB 16
#define LN_EPS 1e-5f

// ---------------- static device scratch ----------------
__device__ float g_basis[(size_t)MROWS * KC];   // 442 MB: 9 Chebyshev terms, interleaved
__device__ float g_hn[(size_t)MROWS * FF];      // 49 MB: post-LN hidden
__device__ float g_Wcat[KC * 128];              // stacked weights (z|h), tf32-rounded
__device__ int   g_pptr_src[NN + 1], g_pptr_dst[NN + 1];  // padded CSR offsets (mult of 4)
__device__ __align__(16) unsigned short g_i16_dst[EPAD];  // by-dst, stores src (pad: idx 0, w 0)
__device__ __align__(16) unsigned short g_i16_src[EPAD];  // by-src, stores dst
__device__ __align__(16) float g_wq_dst[EPAD];            // 1/deg_out[src], pads 0
__device__ __align__(16) float g_wq_src[EPAD];            // 1.0, pads 0
__device__ float g_inv_in[NN];

__device__ __forceinline__ uint32_t f2tf32(float f) {
    uint32_t u;
    asm("cvt.rna.tf32.f32 %0, %1;" : "=r"(u) : "f"(f));
    return u;
}

__device__ __forceinline__ void mma_tf32(float c[4], const uint32_t a[4],
                                         uint32_t b0, uint32_t b1) {
    asm volatile(
        "mma.sync.aligned.m16n8k8.row.col.f32.tf32.tf32.f32 "
        "{%0,%1,%2,%3}, {%4,%5,%6,%7}, {%8,%9}, {%0,%1,%2,%3};"
        : "+f"(c[0]), "+f"(c[1]), "+f"(c[2]), "+f"(c[3])
        : "r"(a[0]), "r"(a[1]), "r"(a[2]), "r"(a[3]), "r"(b0), "r"(b1));
}

// ---------------- single-block CSR setup ----------------
__global__ void __launch_bounds__(1024) setup_kernel(const int* __restrict__ ei) {
    __shared__ int s_cnt_src[NN], s_cnt_dst[NN];
    __shared__ int s_ptr_src[NN + 1], s_ptr_dst[NN + 1];
    __shared__ int s_fill_src[NN], s_fill_dst[NN];
    int tid = threadIdx.x;
    for (int i = tid; i < NN; i += 1024) {
        s_cnt_src[i] = 0; s_cnt_dst[i] = 0;
        s_fill_src[i] = 0; s_fill_dst[i] = 0;
    }
    __syncthreads();
    for (int e = tid; e < EE; e += 1024) {
        atomicAdd(&s_cnt_src[ei[e]], 1);
        atomicAdd(&s_cnt_dst[ei[EE + e]], 1);
    }
    __syncthreads();
    if (tid == 0) {
        int s = 0, t = 0;
        for (int n = 0; n < NN; n++) {
            s_ptr_src[n] = s; s += (s_cnt_src[n] + 3) & ~3;
            s_ptr_dst[n] = t; t += (s_cnt_dst[n] + 3) & ~3;
        }
        s_ptr_src[NN] = s; s_ptr_dst[NN] = t;
    }
    __syncthreads();
    for (int i = tid; i <= NN; i += 1024) {
        g_pptr_src[i] = s_ptr_src[i];
        g_pptr_dst[i] = s_ptr_dst[i];
    }
    for (int n = tid; n < NN; n += 1024)
        g_inv_in[n] = 1.0f / (float)s_cnt_dst[n];
    for (int i = tid; i < EPAD; i += 1024) {
        g_i16_dst[i] = 0; g_i16_src[i] = 0;
        g_wq_dst[i] = 0.f; g_wq_src[i] = 0.f;
    }
    __syncthreads();
    for (int e = tid; e < EE; e += 1024) {
        int s = ei[e], d = ei[EE + e];
        int p = atomicAdd(&s_fill_dst[d], 1);
        int slot = s_ptr_dst[d] + p;
        g_i16_dst[slot] = (unsigned short)s;
        g_wq_dst[slot] = 1.0f / (float)s_cnt_src[s];   // 1/deg_out[src]
        int q = atomicAdd(&s_fill_src[s], 1);
        int slot2 = s_ptr_src[s] + q;
        g_i16_src[slot2] = (unsigned short)d;
        g_wq_src[slot2] = 1.0f;
    }
}

// ---------------- weight stacking ----------------
__global__ void wcat_kernel(const float* __restrict__ Wz, const float* __restrict__ Wh) {
    int t = blockIdx.x * blockDim.x + threadIdx.x;
    if (t >= KC * 128) return;
    int kk = t >> 7;            // [0,576)
    int j  = t & 127;
    int term = kk / FF;
    int ci   = kk % FF;
    const float* W = (j < FF) ? Wz : Wh;
    int co = (j < FF) ? j : j - FF;
    float v;
    if (term == 0) {
        v = W[((0 * 5 + 0) * 128 + ci) * 64 + co] + W[((1 * 5 + 0) * 128 + ci) * 64 + co];
    } else if (term <= 4) {
        v = W[((0 * 5 + term) * 128 + ci) * 64 + co];
    } else {
        v = W[((1 * 5 + (term - 4)) * 128 + ci) * 64 + co];
    }
    g_Wcat[kk * 128 + j] = __uint_as_float(f2tf32(v));
}

// ---------------- basis term 0 = X ----------------
__global__ void copy_t0_kernel(const float* __restrict__ x) {
    int i = blockIdx.x * blockDim.x + threadIdx.x;   // float4 index
    if (i < MROWS * FF / 4) {
        int r = i >> 4, f4 = i & 15;
        const float4 v = reinterpret_cast<const float4*>(x)[i];
        *reinterpret_cast<float4*>(&g_basis[(size_t)r * KC + f4 * 4]) = v;
    }
}

// ---------------- vectorized gather propagation (both directions in one launch) ----------------
__global__ void __launch_bounds__(128) prop_pair_kernel(
    int tin_o, int tin_i, int tout_o, int tout_i, int tsub, float alpha)
{
    int tid = threadIdx.x;
    int g = tid >> 4, l = tid & 15;
    int flat = blockIdx.x * 8 + g;        // [0, MROWS)
    int bt = flat / NN, n = flat - bt * NN;
    int dir = blockIdx.y;

    const unsigned short* idx;
    const float* wq;
    int b0, b1, tin, tout;
    if (dir == 0) {
        idx = g_i16_dst; wq = g_wq_dst;
        b0 = g_pptr_dst[n]; b1 = g_pptr_dst[n + 1];
        tin = tin_o; tout = tout_o;
    } else {
        idx = g_i16_src; wq = g_wq_src;
        b0 = g_pptr_src[n]; b1 = g_pptr_src[n + 1];
        tin = tin_i; tout = tout_i;
    }

    const char* base = (const char*)(g_basis + (size_t)bt * NN * KC + tin * FF) + l * 16;
    float4 acc = make_float4(0.f, 0.f, 0.f, 0.f);

    for (int e = b0; e < b1; e += 4) {
        uint2 q = *reinterpret_cast<const uint2*>(idx + e);
        float4 w = *reinterpret_cast<const float4*>(wq + e);
        int i0 = q.x & 0xffff, i1 = q.x >> 16;
        int i2 = q.y & 0xffff, i3 = q.y >> 16;
        float4 v0 = __ldg(reinterpret_cast<const float4*>(base + (size_t)i0 * (KC * 4)));
        float4 v1 = __ldg(reinterpret_cast<const float4*>(base + (size_t)i1 * (KC * 4)));
        float4 v2 = __ldg(reinterpret_cast<const float4*>(base + (size_t)i2 * (KC * 4)));
        float4 v3 = __ldg(reinterpret_cast<const float4*>(base + (size_t)i3 * (KC * 4)));
        acc.x += w.x * v0.x + w.y * v1.x + w.z * v2.x + w.w * v3.x;
        acc.y += w.x * v0.y + w.y * v1.y + w.z * v2.y + w.w * v3.y;
        acc.z += w.x * v0.z + w.y * v1.z + w.z * v2.z + w.w * v3.z;
        acc.w += w.x * v0.w + w.y * v1.w + w.z * v2.w + w.w * v3.w;
    }

    float scale = dir ? alpha * g_inv_in[n] : alpha;
    float4 r = make_float4(scale * acc.x, scale * acc.y, scale * acc.z, scale * acc.w);
    float* orow = g_basis + (size_t)flat * KC;
    if (tsub >= 0) {
        float4 s4 = *reinterpret_cast<const float4*>(orow + tsub * FF + l * 4);
        r.x -= s4.x; r.y -= s4.y; r.z -= s4.z; r.w -= s4.w;
    }
    *reinterpret_cast<float4*>(orow + tout * FF + l * 4) = r;
}

// ---------------- tf32 tensor-core GEMM (192000x576 @ 576x128) + gate + LN ----------------
// Conflict-free smem: As stride 20 (banks 20r+tg cover all 32), Bs stride 136
// (banks 8r+g cover all 32). Double-buffered smem + register prefetch: 1 sync/tile.
#define TM 128
#define TKC 16
#define AS_STR 20
#define BS_STR 136
__global__ void __launch_bounds__(256) gemm_tc_kernel(
    const float* __restrict__ bz, const float* __restrict__ bh,
    const float* __restrict__ lng, const float* __restrict__ lnb)
{
    __shared__ uint32_t As[2][TM * AS_STR];
    __shared__ uint32_t Bs[2][TKC * BS_STR];

    int tid = threadIdx.x;
    int w = tid >> 5, lane = tid & 31;
    int g = lane >> 2, tg = lane & 3;
    int block_row = blockIdx.x * TM;

    float acc[16][4];
#pragma unroll
    for (int j = 0; j < 16; j++)
#pragma unroll
        for (int i = 0; i < 4; i++) acc[j][i] = 0.f;

    int arow = tid >> 1;            // A-load: 2 threads per row, 8 floats each
    int acol = (tid & 1) * 8;
    int brow = tid >> 4;            // B-load: 16 threads per row, 8 floats each
    int bcol = (tid & 15) * 8;
    const float* aptr = &g_basis[(size_t)(block_row + arow) * KC + acol];
    const float* bptr = &g_Wcat[brow * 128 + bcol];

    // prologue prefetch (tile 0)
    float4 pa0 = *reinterpret_cast<const float4*>(aptr);
    float4 pa1 = *reinterpret_cast<const float4*>(aptr + 4);
    float4 pb0 = *reinterpret_cast<const float4*>(bptr);
    float4 pb1 = *reinterpret_cast<const float4*>(bptr + 4);

    const int NT = KC / TKC;   // 36 tiles
#pragma unroll 1
    for (int t = 0; t < NT; t++) {
        int buf = t & 1;
        // store staged regs (tf32-converted, vectorized STS.128)
        uint4 av0, av1;
        av0.x = f2tf32(pa0.x); av0.y = f2tf32(pa0.y); av0.z = f2tf32(pa0.z); av0.w = f2tf32(pa0.w);
        av1.x = f2tf32(pa1.x); av1.y = f2tf32(pa1.y); av1.z = f2tf32(pa1.z); av1.w = f2tf32(pa1.w);
        *reinterpret_cast<uint4*>(&As[buf][arow * AS_STR + acol])     = av0;
        *reinterpret_cast<uint4*>(&As[buf][arow * AS_STR + acol + 4]) = av1;
        *reinterpret_cast<uint4*>(&Bs[buf][brow * BS_STR + bcol])     =
            make_uint4(__float_as_uint(pb0.x), __float_as_uint(pb0.y),
                       __float_as_uint(pb0.z), __float_as_uint(pb0.w));
        *reinterpret_cast<uint4*>(&Bs[buf][brow * BS_STR + bcol + 4]) =
            make_uint4(__float_as_uint(pb1.x), __float_as_uint(pb1.y),
                       __float_as_uint(pb1.z), __float_as_uint(pb1.w));
        __syncthreads();

        if (t + 1 < NT) {   // prefetch next tile while MMAs run
            int k1 = (t + 1) * TKC;
            pa0 = *reinterpret_cast<const float4*>(aptr + k1);
            pa1 = *reinterpret_cast<const float4*>(aptr + k1 + 4);
            pb0 = *reinterpret_cast<const float4*>(bptr + k1 * 128);
            pb1 = *reinterpret_cast<const float4*>(bptr + k1 * 128 + 4);
        }

        const uint32_t* Ab = &As[buf][0];
        const uint32_t* Bb = &Bs[buf][0];
#pragma unroll
        for (int kb = 0; kb < TKC; kb += 8) {
            uint32_t a[4];
            a[0] = Ab[(w * 16 + g) * AS_STR + kb + tg];
            a[1] = Ab[(w * 16 + g + 8) * AS_STR + kb + tg];
            a[2] = Ab[(w * 16 + g) * AS_STR + kb + tg + 4];
            a[3] = Ab[(w * 16 + g + 8) * AS_STR + kb + tg + 4];
#pragma unroll
            for (int j = 0; j < 16; j++) {
                uint32_t bb0 = Bb[(kb + tg) * BS_STR + j * 8 + g];
                uint32_t bb1 = Bb[(kb + tg + 4) * BS_STR + j * 8 + g];
                mma_tf32(acc[j], a, bb0, bb1);
            }
        }
        // no second sync needed: next iteration writes the other buffer,
        // and its own pre-compute sync protects the store.
        __syncthreads();
    }

    // ---- epilogue: gate + LayerNorm, register-resident ----
#pragma unroll
    for (int rs = 0; rs < 2; rs++) {
        int row = block_row + w * 16 + g + rs * 8;
        float gv[8][2];
        float sum = 0.f, sq = 0.f;
#pragma unroll
        for (int j = 0; j < 8; j++) {
#pragma unroll
            for (int s = 0; s < 2; s++) {
                int col = j * 8 + tg * 2 + s;
                float vz = acc[j][rs * 2 + s] + __ldg(bz + col);
                float vh = acc[j + 8][rs * 2 + s] + __ldg(bh + col);
                float z = 1.f / (1.f + expf(-vz));
                float val = fmaxf(0.f, (1.f - z) * tanhf(vh));
                gv[j][s] = val;
                sum += val; sq += val * val;
            }
        }
        sum += __shfl_xor_sync(0xffffffffu, sum, 1);
        sq  += __shfl_xor_sync(0xffffffffu, sq, 1);
        sum += __shfl_xor_sync(0xffffffffu, sum, 2);
        sq  += __shfl_xor_sync(0xffffffffu, sq, 2);
        float mu = sum * (1.f / 64.f);
        float var = fmaxf(sq * (1.f / 64.f) - mu * mu, 0.f);
        float rstd = rsqrtf(var + LN_EPS);
        float* orow = g_hn + (size_t)row * FF;
#pragma unroll
        for (int j = 0; j < 8; j++) {
            int col = j * 8 + tg * 2;
            float2 o;
            o.x = (gv[j][0] - mu) * rstd * __ldg(lng + col)     + __ldg(lnb + col);
            o.y = (gv[j][1] - mu) * rstd * __ldg(lng + col + 1) + __ldg(lnb + col + 1);
            *reinterpret_cast<float2*>(orow + col) = o;
        }
    }
}

// ---------------- final linear head ----------------
__global__ void out_init_kernel(float* __restrict__ out, const float* __restrict__ lb) {
    int i = threadIdx.x;
    if (i < BB * CC) out[i] = lb[i % CC];
}

#define CH 1024
__global__ void __launch_bounds__(256) final_linear_kernel(
    const float* __restrict__ lin_w, float* __restrict__ out)
{
    __shared__ float ws[CC][CH];
    __shared__ float red[8][CC];
    int base = blockIdx.x * CH;   // 750 blocks * 1024 = 768000
    int tid = threadIdx.x;
    for (int i = tid; i < CC * CH; i += 256) {
        int c = i / CH, o = i % CH;
        ws[c][o] = lin_w[(size_t)c * LDIM + base + o];
    }
    __syncthreads();
    int w = tid >> 5, lane = tid & 31;
    for (int b = 0; b < BB; b++) {
        float a[CC];
#pragma unroll
        for (int c = 0; c < CC; c++) a[c] = 0.f;
        const float* hb = g_hn + (size_t)b * LDIM + base;
        for (int i = tid; i < CH; i += 256) {
            float hv = hb[i];
#pragma unroll
            for (int c = 0; c < CC; c++) a[c] += hv * ws[c][i];
        }
#pragma unroll
        for (int o = 16; o; o >>= 1)
#pragma unroll
            for (int c = 0; c < CC; c++) a[c] += __shfl_down_sync(0xffffffffu, a[c], o);
        if (lane == 0)
#pragma unroll
            for (int c = 0; c < CC; c++) red[w][c] = a[c];
        __syncthreads();
        if (tid < CC) {
            float s = 0.f;
#pragma unroll
            for (int ww = 0; ww < 8; ww++) s += red[ww][tid];
            atomicAdd(&out[b * CC + tid], s);
        }
        __syncthreads();
    }
}

// ---------------- launch ----------------
extern "C" void kernel_launch(void* const* d_in, const int* in_sizes, int n_in,
                              void* d_out, int out_size) {
    const float* x    = (const float*)d_in[0];
    const int*   ei   = (const int*)d_in[1];
    const float* Wz   = (const float*)d_in[2];
    const float* bz   = (const float*)d_in[3];
    // d_in[4], d_in[5] = W_r, b_r -> dead code (h0 == 0)
    const float* Wh   = (const float*)d_in[6];
    const float* bh   = (const float*)d_in[7];
    const float* lng  = (const float*)d_in[8];
    const float* lnb  = (const float*)d_in[9];
    const float* linw = (const float*)d_in[10];
    const float* linb = (const float*)d_in[11];
    float* out = (float*)d_out;

    setup_kernel<<<1, 1024>>>(ei);                                   // launch 1
    wcat_kernel<<<(KC * 128 + 255) / 256, 256>>>(Wz, Wh);            // launch 2
    copy_t0_kernel<<<(MROWS * FF / 4 + 255) / 256, 256>>>(x);        // launch 3

    dim3 pgrid(MROWS / 8, 2);
    // terms: 0=X, 1..4 = out-chain, 5..8 = in-chain (shared Tx0 history = out-chain terms)
    prop_pair_kernel<<<pgrid, 128>>>(0, 0, 1, 5, -1, 1.0f);          // launch 4 (profiled slot)
    prop_pair_kernel<<<pgrid, 128>>>(1, 5, 2, 6, 0, 2.0f);
    prop_pair_kernel<<<pgrid, 128>>>(2, 6, 3, 7, 1, 2.0f);
    prop_pair_kernel<<<pgrid, 128>>>(3, 7, 4, 8, 2, 2.0f);

    gemm_tc_kernel<<<MROWS / TM, 256>>>(bz, bh, lng, lnb);

    out_init_kernel<<<1, 256>>>(out, linb);
    final_linear_kernel<<<LDIM / CH, 256>>>(linw, out);
}